// round 4
// baseline (speedup 1.0000x reference)
#include <cuda_runtime.h>

// ConditionalPatchSlicedTransport — fused per-patch transport, smem-LUT splines.
// R4: occupancy push — __launch_bounds__(256,3), register diet (in-place dyv,
// x reloaded from gmem at store time), eval loop unroll 4.

#define NSAMP   2048
#define NDIMX   3072
#define NTRANSX 3072
#define NBIN    200
#define NKER    192
#define NCLASS  10
#define TPB     256
#define NLUT    512

__device__ int   g_idx[NSAMP];
__device__ int   g_off[NCLASS + 1];
__device__ float g_ljp[NSAMP * NKER];

// ---------------------------------------------------------------------------
__global__ void prep_kernel(const int* __restrict__ label) {
    __shared__ int scnt[NCLASS], soff[NCLASS], sfill[NCLASS];
    int tid = threadIdx.x;
    if (tid < NCLASS) { scnt[tid] = 0; sfill[tid] = 0; }
    __syncthreads();

    int n0 = tid, n1 = tid + 1024;
    int c0 = label[n0];
    int c1 = label[n1];
    atomicAdd(&scnt[c0], 1);
    atomicAdd(&scnt[c1], 1);
    __syncthreads();

    if (tid == 0) {
        int acc = 0;
        for (int c = 0; c < NCLASS; c++) {
            soff[c] = acc;
            g_off[c] = acc;
            acc += scnt[c];
        }
        g_off[NCLASS] = acc;
    }
    __syncthreads();

    int p0 = atomicAdd(&sfill[c0], 1);
    g_idx[soff[c0] + p0] = n0;
    int p1 = atomicAdd(&sfill[c1], 1);
    g_idx[soff[c1] + p1] = n1;
}

// ---------------------------------------------------------------------------
// smem: float4 knots[16*200] | float Wa[256] | float Wt[256] | u8 lut[16*512]
// ---------------------------------------------------------------------------
#define SMEM_KNOTS (16 * NBIN * 16)          // 51200 B
#define SMEM_W     (2 * 256 * 4)             // 2048 B
#define SMEM_LUT   (16 * NLUT)               // 8192 B
#define SMEM_TOTAL (SMEM_KNOTS + SMEM_W + SMEM_LUT)

__global__ void __launch_bounds__(TPB, 3) main_kernel(
    const float* __restrict__ data,   // (NSAMP, NDIMX)
    const float* __restrict__ Wb,     // (NKER, 16, 16)
    const float* __restrict__ kx,     // (NCLASS, NTRANSX, NBIN)
    const float* __restrict__ ky,
    const float* __restrict__ kd,
    float* __restrict__ out)          // (NSAMP, NDIMX)
{
    extern __shared__ float smem[];
    float4*        st   = (float4*)smem;                      // [16*200]
    float*         Wa   = smem + (SMEM_KNOTS / 4);            // [256]
    float*         Wt   = Wa + 256;                           // [256]
    unsigned char* slut = (unsigned char*)(Wt + 256);         // [16*512]

    const int k   = blockIdx.x;
    const int c   = blockIdx.y;
    const int tid = threadIdx.x;

    // interleaved knots: (x_j, y_j, d_j, 1/(x_{j+1}-x_j))
    const size_t kb = ((size_t)c * NTRANSX + (size_t)k * 16) * NBIN;
    for (int idx = tid; idx < 16 * NBIN; idx += TPB) {
        int j = idx % NBIN;
        float xj = __ldg(kx + kb + idx);
        float xn = (j < NBIN - 1) ? __ldg(kx + kb + idx + 1) : (xj + 1.0f);
        float yj = __ldg(ky + kb + idx);
        float dj = __ldg(kd + kb + idx);
        st[idx] = make_float4(xj, yj, dj, 1.0f / (xn - xj));
    }
    {
        int s = tid >> 4, i = tid & 15;
        float v = Wb[k * 256 + tid];   // W[k][s][i]
        Wa[tid] = v;
        Wt[i * 16 + s] = v;
    }
    {
        unsigned int* sl = (unsigned int*)slut;
        for (int idx = tid; idx < SMEM_LUT / 4; idx += TPB) sl[idx] = 0u;
    }
    __syncthreads();

    // build LUT from smem knots: item (i, j) fills [qs(x_j), qs(x_{j+1}))
    // with min(j, NBIN-2); ranges partition -> race-free.
    for (int item = tid; item < 16 * NBIN; item += TPB) {
        int i = item / NBIN;
        int j = item - i * NBIN;
        float xj = st[i * NBIN + j].x;
        int q0 = (int)ceilf((xj + 4.0f) * 64.0f);
        q0 = min(max(q0, 0), NLUT);
        int q1;
        if (j < NBIN - 1) {
            float xn = st[i * NBIN + j + 1].x;
            q1 = min(max((int)ceilf((xn + 4.0f) * 64.0f), 0), NLUT);
        } else {
            q1 = NLUT;
        }
        unsigned char v = (unsigned char)min(j, NBIN - 2);
        for (int q = q0; q < q1; q++) slut[i * NLUT + q] = v;
    }
    __syncthreads();

    const int off = g_off[c];
    const int cnt = g_off[c + 1] - off;

    const int nh  = k / 24;
    const int rem = k - nh * 24;
    const int nw  = rem / 3;
    const int ch  = rem - nw * 3;
    const int pixbase = nh * 4 * 96 + nw * 4 * 3 + ch;

    const float4* Wa4 = (const float4*)Wa;
    const float4* Wt4 = (const float4*)Wt;

    for (int sbase = 0; sbase < cnt; sbase += TPB) {
        int sidx = sbase + tid;
        if (sidx >= cnt) break;
        const int n = g_idx[off + sidx];
        const float* __restrict__ drow = data + (size_t)n * NDIMX;

        // u = x @ W  (x read streaming; xv not kept live past this phase)
        float4 ua0 = make_float4(0.f, 0.f, 0.f, 0.f);
        float4 ua1 = ua0, ua2 = ua0, ua3 = ua0;
#pragma unroll
        for (int s = 0; s < 16; s++) {
            int p = pixbase + (s >> 2) * 96 + (s & 3) * 3;
            float xs = __ldg(drow + p);
            float4 w0 = Wa4[s * 4 + 0];
            float4 w1 = Wa4[s * 4 + 1];
            float4 w2 = Wa4[s * 4 + 2];
            float4 w3 = Wa4[s * 4 + 3];
            ua0.x = fmaf(xs, w0.x, ua0.x); ua0.y = fmaf(xs, w0.y, ua0.y);
            ua0.z = fmaf(xs, w0.z, ua0.z); ua0.w = fmaf(xs, w0.w, ua0.w);
            ua1.x = fmaf(xs, w1.x, ua1.x); ua1.y = fmaf(xs, w1.y, ua1.y);
            ua1.z = fmaf(xs, w1.z, ua1.z); ua1.w = fmaf(xs, w1.w, ua1.w);
            ua2.x = fmaf(xs, w2.x, ua2.x); ua2.y = fmaf(xs, w2.y, ua2.y);
            ua2.z = fmaf(xs, w2.z, ua2.z); ua2.w = fmaf(xs, w2.w, ua2.w);
            ua3.x = fmaf(xs, w3.x, ua3.x); ua3.y = fmaf(xs, w3.y, ua3.y);
            ua3.z = fmaf(xs, w3.z, ua3.z); ua3.w = fmaf(xs, w3.w, ua3.w);
        }
        float u[16];
        u[0] = ua0.x; u[1] = ua0.y; u[2]  = ua0.z; u[3]  = ua0.w;
        u[4] = ua1.x; u[5] = ua1.y; u[6]  = ua1.z; u[7]  = ua1.w;
        u[8] = ua2.x; u[9] = ua2.y; u[10] = ua2.z; u[11] = ua2.w;
        u[12] = ua3.x; u[13] = ua3.y; u[14] = ua3.z; u[15] = ua3.w;

        // splines: u[i] is overwritten in place with dyv[i] = y_i - u_i
        float prod0 = 1.0f, prod1 = 1.0f;
#pragma unroll 4
        for (int i = 0; i < 16; i++) {
            const float4* __restrict__ ti = st + i * NBIN;
            float x = u[i];

            float4 t0 = ti[0];
            float4 tK = ti[NBIN - 1];
            float lo = t0.x, hi = tK.x;
            float xc = fminf(fmaxf(x, lo), hi);

            int q = (int)((xc + 4.0f) * 64.0f);
            q = max(0, min(NLUT - 1, q));
            int kk = (int)slut[i * NLUT + q];
            while (kk < NBIN - 2 && ti[kk + 1].x <= xc) kk++;
            while (kk > 0 && ti[kk].x > xc) kk--;

            float4 a = ti[kk];
            float4 b = ti[kk + 1];

            float dyk  = b.y - a.y;
            float s_   = dyk * a.w;
            float xi   = (xc - a.x) * a.w;
            float om   = 1.0f - xi;
            float xi2  = xi * xi;
            float xiom = xi * om;
            float denom = fmaf(fmaf(-2.0f, s_, b.z + a.z), xiom, s_);
            float invd  = __fdividef(1.0f, denom);
            float ys    = fmaf(dyk * invd, fmaf(s_, xi2, a.z * xiom), a.y);
            float numer = fmaf(b.z, xi2, fmaf(2.0f * s_, xiom, a.z * om * om));
            float t1    = s_ * invd;
            float arg   = t1 * t1 * numer;   // = s^2 * numer / denom^2

            float yv, larg;
            if (x < lo) {
                yv = fmaf(x - lo, t0.z, t0.y);  larg = t0.z;
            } else if (x > hi) {
                yv = fmaf(x - hi, tK.z, tK.y);  larg = tK.z;
            } else {
                yv = ys;                        larg = arg;
            }
            if (i < 8) prod0 *= larg; else prod1 *= larg;
            u[i] = yv - x;   // dyv in place
        }
        float ljsum = __logf(prod0) + __logf(prod1);

        // out_j = x_j + sum_i dyv_i * W[j][i]   (x_j reloaded, L1/L2-hot)
        float4 oa0 = make_float4(0.f, 0.f, 0.f, 0.f);
        float4 oa1 = oa0, oa2 = oa0, oa3 = oa0;
#pragma unroll
        for (int i = 0; i < 16; i++) {
            float dv = u[i];
            float4 w0 = Wt4[i * 4 + 0];
            float4 w1 = Wt4[i * 4 + 1];
            float4 w2 = Wt4[i * 4 + 2];
            float4 w3 = Wt4[i * 4 + 3];
            oa0.x = fmaf(dv, w0.x, oa0.x); oa0.y = fmaf(dv, w0.y, oa0.y);
            oa0.z = fmaf(dv, w0.z, oa0.z); oa0.w = fmaf(dv, w0.w, oa0.w);
            oa1.x = fmaf(dv, w1.x, oa1.x); oa1.y = fmaf(dv, w1.y, oa1.y);
            oa1.z = fmaf(dv, w1.z, oa1.z); oa1.w = fmaf(dv, w1.w, oa1.w);
            oa2.x = fmaf(dv, w2.x, oa2.x); oa2.y = fmaf(dv, w2.y, oa2.y);
            oa2.z = fmaf(dv, w2.z, oa2.z); oa2.w = fmaf(dv, w2.w, oa2.w);
            oa3.x = fmaf(dv, w3.x, oa3.x); oa3.y = fmaf(dv, w3.y, oa3.y);
            oa3.z = fmaf(dv, w3.z, oa3.z); oa3.w = fmaf(dv, w3.w, oa3.w);
        }
        float ov[16];
        ov[0] = oa0.x; ov[1] = oa0.y; ov[2]  = oa0.z; ov[3]  = oa0.w;
        ov[4] = oa1.x; ov[5] = oa1.y; ov[6]  = oa1.z; ov[7]  = oa1.w;
        ov[8] = oa2.x; ov[9] = oa2.y; ov[10] = oa2.z; ov[11] = oa2.w;
        ov[12] = oa3.x; ov[13] = oa3.y; ov[14] = oa3.z; ov[15] = oa3.w;

        float* __restrict__ orow = out + (size_t)n * NDIMX;
#pragma unroll
        for (int j = 0; j < 16; j++) {
            int p = pixbase + (j >> 2) * 96 + (j & 3) * 3;
            orow[p] = __ldg(drow + p) + ov[j];
        }

        g_ljp[n * NKER + k] = ljsum;
    }
}

// ---------------------------------------------------------------------------
__global__ void reduce_lj(float* __restrict__ logj) {
    int gtid = blockIdx.x * blockDim.x + threadIdx.x;
    int w    = gtid >> 5;
    int lane = gtid & 31;
    if (w >= NSAMP) return;
    const float* __restrict__ p = g_ljp + (size_t)w * NKER;
    float s = 0.f;
#pragma unroll
    for (int q = 0; q < NKER / 32; q++) s += p[q * 32 + lane];
#pragma unroll
    for (int o = 16; o > 0; o >>= 1) s += __shfl_xor_sync(0xffffffffu, s, o);
    if (lane == 0) logj[w] = s;
}

// ---------------------------------------------------------------------------
extern "C" void kernel_launch(void* const* d_in, const int* in_sizes, int n_in,
                              void* d_out, int out_size) {
    const float* data  = (const float*)d_in[0];
    const int*   label = (const int*)d_in[1];
    const float* Wb    = (const float*)d_in[2];
    const float* kxp   = (const float*)d_in[3];
    const float* kyp   = (const float*)d_in[4];
    const float* kdp   = (const float*)d_in[5];

    float* out  = (float*)d_out;                      // (2048, 3072)
    float* logj = out + (size_t)NSAMP * NDIMX;        // (2048,)

    static bool attr_done = false;
    if (!attr_done) {
        cudaFuncSetAttribute(main_kernel,
                             cudaFuncAttributeMaxDynamicSharedMemorySize,
                             SMEM_TOTAL);
        attr_done = true;
    }

    prep_kernel<<<1, 1024>>>(label);
    main_kernel<<<dim3(NKER, NCLASS), TPB, SMEM_TOTAL>>>(data, Wb, kxp, kyp, kdp, out);
    reduce_lj<<<(NSAMP * 32 + TPB - 1) / TPB, TPB>>>(logj);
}

// round 5
// speedup vs baseline: 1.2818x; 1.2818x over previous
#include <cuda_runtime.h>

// ConditionalPatchSlicedTransport — R5: lane-per-transform decomposition.
// 16 lanes (half-warp) = one sample-patch. Lane l owns transform l:
// W column+row in registers, one spline eval per sample, shfl matmuls,
// shfl-butterfly product for the log-Jacobian.

#define NSAMP   2048
#define NDIMX   3072
#define NTRANSX 3072
#define NBIN    200
#define NBINP   201      /* padded float4 row stride (bank spread) */
#define NKER    192
#define NCLASS  10
#define TPB     256
#define NLUT    512
#define LUTSTR  516      /* padded byte row stride (bank spread) */

__device__ int   g_idx[NSAMP];
__device__ int   g_off[NCLASS + 1];
__device__ float g_ljp[NSAMP * NKER];

// ---------------------------------------------------------------------------
__global__ void prep_kernel(const int* __restrict__ label) {
    __shared__ int scnt[NCLASS], soff[NCLASS], sfill[NCLASS];
    int tid = threadIdx.x;
    if (tid < NCLASS) { scnt[tid] = 0; sfill[tid] = 0; }
    __syncthreads();

    int n0 = tid, n1 = tid + 1024;
    int c0 = label[n0];
    int c1 = label[n1];
    atomicAdd(&scnt[c0], 1);
    atomicAdd(&scnt[c1], 1);
    __syncthreads();

    if (tid == 0) {
        int acc = 0;
        for (int c = 0; c < NCLASS; c++) {
            soff[c] = acc;
            g_off[c] = acc;
            acc += scnt[c];
        }
        g_off[NCLASS] = acc;
    }
    __syncthreads();

    int p0 = atomicAdd(&sfill[c0], 1);
    g_idx[soff[c0] + p0] = n0;
    int p1 = atomicAdd(&sfill[c1], 1);
    g_idx[soff[c1] + p1] = n1;
}

// ---------------------------------------------------------------------------
// smem: float4 knots[16*NBINP] | u8 lut[16*LUTSTR]
// ---------------------------------------------------------------------------
#define SMEM_KNOTS (16 * NBINP * 16)         // 51456 B
#define SMEM_LUT   (16 * LUTSTR)             // 8256 B
#define SMEM_TOTAL (SMEM_KNOTS + SMEM_LUT)   // 59712 B -> 3 blocks/SM

__global__ void __launch_bounds__(TPB) main_kernel(
    const float* __restrict__ data,   // (NSAMP, NDIMX)
    const float* __restrict__ Wb,     // (NKER, 16, 16)
    const float* __restrict__ kx,     // (NCLASS, NTRANSX, NBIN)
    const float* __restrict__ ky,
    const float* __restrict__ kd,
    float* __restrict__ out)          // (NSAMP, NDIMX)
{
    extern __shared__ float smem[];
    float4*        st   = (float4*)smem;                       // [16*NBINP]
    unsigned char* slut = (unsigned char*)(smem + SMEM_KNOTS / 4);

    const int k   = blockIdx.x;
    const int c   = blockIdx.y;
    const int tid = threadIdx.x;

    // interleaved knots (x_j, y_j, d_j, 1/(x_{j+1}-x_j)), padded row stride
    const size_t kb = ((size_t)c * NTRANSX + (size_t)k * 16) * NBIN;
    for (int idx = tid; idx < 16 * NBIN; idx += TPB) {
        int i = idx / NBIN;
        int j = idx - i * NBIN;
        float xj = __ldg(kx + kb + idx);
        float xn = (j < NBIN - 1) ? __ldg(kx + kb + idx + 1) : (xj + 1.0f);
        float yj = __ldg(ky + kb + idx);
        float dj = __ldg(kd + kb + idx);
        st[i * NBINP + j] = make_float4(xj, yj, dj, 1.0f / (xn - xj));
    }
    {
        unsigned int* sl = (unsigned int*)slut;
        for (int idx = tid; idx < SMEM_LUT / 4; idx += TPB) sl[idx] = 0u;
    }
    __syncthreads();

    // LUT: item (i,j) fills [qs(x_j), qs(x_{j+1})) with min(j, NBIN-2)
    for (int item = tid; item < 16 * NBIN; item += TPB) {
        int i = item / NBIN;
        int j = item - i * NBIN;
        float xj = st[i * NBINP + j].x;
        int q0 = min(max((int)ceilf((xj + 4.0f) * 64.0f), 0), NLUT);
        int q1;
        if (j < NBIN - 1) {
            float xn = st[i * NBINP + j + 1].x;
            q1 = min(max((int)ceilf((xn + 4.0f) * 64.0f), 0), NLUT);
        } else {
            q1 = NLUT;
        }
        unsigned char v = (unsigned char)min(j, NBIN - 2);
        for (int q = q0; q < q1; q++) slut[i * LUTSTR + q] = v;
    }
    __syncthreads();

    const int group = tid >> 4;    // 16 groups, one sample each per iteration
    const int lane  = tid & 15;    // transform index within the patch

    // W column (for u = x@W) and row (for dv@W^T), registers, loaded once
    float Wcol[16], Wrow[16];
#pragma unroll
    for (int s = 0; s < 16; s++) {
        Wcol[s] = __ldg(Wb + k * 256 + s * 16 + lane);   // W[s][lane]
        Wrow[s] = __ldg(Wb + k * 256 + lane * 16 + s);   // W[lane][s]
    }

    // per-lane loop invariants
    const float4* __restrict__ ti = st + lane * NBINP;
    const unsigned char* __restrict__ lrow = slut + lane * LUTSTR;
    const float4 t0 = ti[0];
    const float4 tK = ti[NBIN - 1];
    const float lo = t0.x, hi = tK.x;

    const int off = g_off[c];
    const int cnt = g_off[c + 1] - off;

    const int nh  = k / 24;
    const int rem = k - nh * 24;
    const int nw  = rem / 3;
    const int ch  = rem - nw * 3;
    const int pix = nh * 4 * 96 + nw * 4 * 3 + ch
                  + (lane >> 2) * 96 + (lane & 3) * 3;

    const int nIters = (cnt + 15) >> 4;

    // software pipeline: prefetch sample index + pixel
    int   nCur = 0;
    float xCur = 0.f;
    bool  aCur = (group < cnt);
    if (aCur) {
        nCur = g_idx[off + group];
        xCur = __ldg(data + (size_t)nCur * NDIMX + pix);
    }

    for (int it = 0; it < nIters; it++) {
        // prefetch next
        int   nNxt = 0;
        float xNxt = 0.f;
        int   sNxt = (it + 1) * 16 + group;
        bool  aNxt = (sNxt < cnt);
        if (aNxt) {
            nNxt = g_idx[off + sNxt];
            xNxt = __ldg(data + (size_t)nNxt * NDIMX + pix);
        }

        // ---- u = x @ W (shfl broadcasts within the 16-lane group) ----
        float u = 0.f;
#pragma unroll
        for (int s = 0; s < 16; s++)
            u = fmaf(__shfl_sync(0xffffffffu, xCur, s, 16), Wcol[s], u);

        // ---- spline eval (one per lane) ----
        float xc = fminf(fmaxf(u, lo), hi);
        int q = (int)((xc + 4.0f) * 64.0f);
        q = max(0, min(NLUT - 1, q));
        int kk = (int)lrow[q];
        while (kk < NBIN - 2 && ti[kk + 1].x <= xc) kk++;
        while (kk > 0 && ti[kk].x > xc) kk--;

        float4 a = ti[kk];
        float4 b = ti[kk + 1];

        float dyk  = b.y - a.y;
        float s_   = dyk * a.w;
        float xi   = (xc - a.x) * a.w;
        float om   = 1.0f - xi;
        float xi2  = xi * xi;
        float xiom = xi * om;
        float denom = fmaf(fmaf(-2.0f, s_, b.z + a.z), xiom, s_);
        float invd  = __fdividef(1.0f, denom);
        float ys    = fmaf(dyk * invd, fmaf(s_, xi2, a.z * xiom), a.y);
        float numer = fmaf(b.z, xi2, fmaf(2.0f * s_, xiom, a.z * om * om));
        float t1    = s_ * invd;
        float arg   = t1 * t1 * numer;      // s^2 * numer / denom^2

        float yv, larg;
        if (u < lo)      { yv = fmaf(u - lo, t0.z, t0.y);  larg = t0.z; }
        else if (u > hi) { yv = fmaf(u - hi, tK.z, tK.y);  larg = tK.z; }
        else             { yv = ys;                        larg = arg;  }

        // ---- log|jac| product across the 16 lanes ----
        float pr = larg;
        pr *= __shfl_xor_sync(0xffffffffu, pr, 8, 16);
        pr *= __shfl_xor_sync(0xffffffffu, pr, 4, 16);
        pr *= __shfl_xor_sync(0xffffffffu, pr, 2, 16);
        pr *= __shfl_xor_sync(0xffffffffu, pr, 1, 16);

        // ---- out = x + (y-u) @ W^T ----
        float dyv = yv - u;
        float ov = 0.f;
#pragma unroll
        for (int i = 0; i < 16; i++)
            ov = fmaf(__shfl_sync(0xffffffffu, dyv, i, 16), Wrow[i], ov);

        if (aCur) {
            out[(size_t)nCur * NDIMX + pix] = xCur + ov;
            if (lane == 0) g_ljp[nCur * NKER + k] = __logf(pr);
        }

        nCur = nNxt; xCur = xNxt; aCur = aNxt;
    }
}

// ---------------------------------------------------------------------------
__global__ void reduce_lj(float* __restrict__ logj) {
    int gtid = blockIdx.x * blockDim.x + threadIdx.x;
    int w    = gtid >> 5;
    int lane = gtid & 31;
    if (w >= NSAMP) return;
    const float* __restrict__ p = g_ljp + (size_t)w * NKER;
    float s = 0.f;
#pragma unroll
    for (int q = 0; q < NKER / 32; q++) s += p[q * 32 + lane];
#pragma unroll
    for (int o = 16; o > 0; o >>= 1) s += __shfl_xor_sync(0xffffffffu, s, o);
    if (lane == 0) logj[w] = s;
}

// ---------------------------------------------------------------------------
extern "C" void kernel_launch(void* const* d_in, const int* in_sizes, int n_in,
                              void* d_out, int out_size) {
    const float* data  = (const float*)d_in[0];
    const int*   label = (const int*)d_in[1];
    const float* Wb    = (const float*)d_in[2];
    const float* kxp   = (const float*)d_in[3];
    const float* kyp   = (const float*)d_in[4];
    const float* kdp   = (const float*)d_in[5];

    float* out  = (float*)d_out;                      // (2048, 3072)
    float* logj = out + (size_t)NSAMP * NDIMX;        // (2048,)

    static bool attr_done = false;
    if (!attr_done) {
        cudaFuncSetAttribute(main_kernel,
                             cudaFuncAttributeMaxDynamicSharedMemorySize,
                             SMEM_TOTAL);
        attr_done = true;
    }

    prep_kernel<<<1, 1024>>>(label);
    main_kernel<<<dim3(NKER, NCLASS), TPB, SMEM_TOTAL>>>(data, Wb, kxp, kyp, kdp, out);
    reduce_lj<<<(NSAMP * 32 + TPB - 1) / TPB, TPB>>>(logj);
}